// round 3
// baseline (speedup 1.0000x reference)
#include <cuda_runtime.h>
#include <math.h>

#define PP 3
#define NN 50000
#define EE 256000
#define CC 5
#define FF 68
#define FE 16
#define FN 64
#define F2 (2*FF)   // 136

// Scratch for scatter-add aggregation: [P, N, C, F] = 51,000,000 floats (204 MB)
__device__ __align__(16) float g_aggr[(size_t)PP*NN*CC*FF];
__device__ int g_is64;   // 1 if edge_index is int64, 0 if int32

__global__ void detect_kernel(const void* __restrict__ ei) {
    // Interpret first 64 entries as int64; valid node ids => int64 data.
    // int32 data reinterpreted as int64 gives values ~hi*2^32 -> out of range.
    const long long* q = (const long long*)ei;
    int ok = 1;
    for (int i = 0; i < 64; ++i) {
        long long v = q[i];
        if (v < 0 || v >= NN) { ok = 0; break; }
    }
    g_is64 = ok;
}

__global__ void zero_kernel() {
    const size_t total = (size_t)PP*NN*CC*FF/4;
    float4* p = (float4*)g_aggr;
    const float4 z = make_float4(0.f, 0.f, 0.f, 0.f);
    for (size_t i = (size_t)blockIdx.x*blockDim.x + threadIdx.x; i < total;
         i += (size_t)gridDim.x*blockDim.x)
        p[i] = z;
}

__device__ __forceinline__ void red4(float* addr, float a, float b, float c, float d) {
    asm volatile("red.global.add.v4.f32 [%0], {%1,%2,%3,%4};"
                 :: "l"(addr), "f"(a), "f"(b), "f"(c), "f"(d) : "memory");
}

// ---------------------------------------------------------------------------
// Edge kernel: one thread per edge. Per-plane edge-MLP weights staged in smem;
// all 32 lanes of a warp read the same weight address (broadcast LDS.128), so
// each weight load is amortized over 32 edges.
// ---------------------------------------------------------------------------
__global__ __launch_bounds__(256) void edge_kernel(
    const float* __restrict__ x, const void* __restrict__ ei,
    const float* __restrict__ We1, const float* __restrict__ be1,
    const float* __restrict__ We2, const float* __restrict__ be2)
{
    __shared__ __align__(16) float sW1[CC*FE*F2];   // 10880 floats = 43.5 KB
    __shared__ float sb1[CC*FE];
    __shared__ float sW2[CC*FE];
    __shared__ float sb2[CC];

    const int p = blockIdx.y;
    for (int i = threadIdx.x; i < CC*FE*F2; i += blockDim.x)
        sW1[i] = We1[(size_t)p*CC*FE*F2 + i];
    for (int i = threadIdx.x; i < CC*FE; i += blockDim.x) {
        sb1[i] = be1[p*CC*FE + i];
        sW2[i] = We2[p*CC*FE + i];
    }
    if (threadIdx.x < CC) sb2[threadIdx.x] = be2[p*CC + threadIdx.x];
    __syncthreads();

    const int is64 = g_is64;
    const long long* ei64 = (const long long*)ei;
    const int*       ei32 = (const int*)ei;
    const size_t base = (size_t)p*2*EE;

    for (int e = blockIdx.x*blockDim.x + threadIdx.x; e < EE;
         e += gridDim.x*blockDim.x) {
        int s, d;
        if (is64) {
            s = (int)ei64[base + e];
            d = (int)ei64[base + EE + e];
        } else {
            s = ei32[base + e];
            d = ei32[base + EE + e];
        }
        const float* xi = x + ((size_t)p*NN + d)*(CC*FF);   // target feats
        const float* xj = x + ((size_t)p*NN + s)*(CC*FF);   // source feats

        float lg[CC];
        #pragma unroll
        for (int c = 0; c < CC; ++c) {
            float acc[FE];
            #pragma unroll
            for (int g = 0; g < FE; ++g) acc[g] = sb1[c*FE + g];

            const float4* mi = (const float4*)(xi + c*FF);
            const float4* mj = (const float4*)(xj + c*FF);
            const float4* w4 = (const float4*)(sW1 + c*FE*F2);

            #pragma unroll 1
            for (int fc = 0; fc < FF/4; ++fc) {
                const float4 u = mi[fc];
                #pragma unroll
                for (int g = 0; g < FE; ++g) {
                    const float4 w = w4[g*(F2/4) + fc];
                    acc[g] += w.x*u.x + w.y*u.y + w.z*u.z + w.w*u.w;
                }
            }
            #pragma unroll 1
            for (int fc = 0; fc < FF/4; ++fc) {
                const float4 u = mj[fc];
                #pragma unroll
                for (int g = 0; g < FE; ++g) {
                    const float4 w = w4[g*(F2/4) + (FF/4) + fc];
                    acc[g] += w.x*u.x + w.y*u.y + w.z*u.z + w.w*u.w;
                }
            }

            float l = sb2[c];
            #pragma unroll
            for (int g = 0; g < FE; ++g)
                l += tanhf(acc[g]) * sW2[c*FE + g];
            lg[c] = l;
        }

        // softmax over classes
        float mx = lg[0];
        #pragma unroll
        for (int c = 1; c < CC; ++c) mx = fmaxf(mx, lg[c]);
        float w[CC];
        float sum = 0.f;
        #pragma unroll
        for (int c = 0; c < CC; ++c) { w[c] = expf(lg[c] - mx); sum += w[c]; }
        const float inv = 1.f / sum;

        // msg = w * x_j, scatter-add to aggr[dst]
        float* ap = g_aggr + ((size_t)p*NN + d)*(CC*FF);
        #pragma unroll
        for (int c = 0; c < CC; ++c) {
            const float wc = w[c] * inv;
            const float4* mj = (const float4*)(xj + c*FF);
            float* a = ap + c*FF;
            #pragma unroll 1
            for (int fc = 0; fc < FF/4; ++fc) {
                const float4 v = mj[fc];
                red4(a + 4*fc, wc*v.x, wc*v.y, wc*v.z, wc*v.w);
            }
        }
    }
}

// ---------------------------------------------------------------------------
// Node kernel: one thread per (node, class). Block owns one (plane, class),
// weights in dynamic smem (51.7 KB). 64 register accumulators for layer 1.
// ---------------------------------------------------------------------------
__global__ __launch_bounds__(256) void node_kernel(
    const float* __restrict__ x,
    const float* __restrict__ Wn1, const float* __restrict__ bn1,
    const float* __restrict__ Wn2, const float* __restrict__ bn2,
    float* __restrict__ out)
{
    extern __shared__ __align__(16) float sm[];
    float* sW1 = sm;                  // FN*F2  = 8704 floats
    float* sW2 = sm + FN*F2;          // FN*FN  = 4096 floats
    float* sb1 = sW2 + FN*FN;         // 64
    float* sb2 = sb1 + FN;            // 64

    const int c = blockIdx.y;
    const int p = blockIdx.z;
    const size_t wo = (size_t)p*CC + c;
    for (int i = threadIdx.x; i < FN*F2; i += blockDim.x) sW1[i] = Wn1[wo*FN*F2 + i];
    for (int i = threadIdx.x; i < FN*FN; i += blockDim.x) sW2[i] = Wn2[wo*FN*FN + i];
    for (int i = threadIdx.x; i < FN; i += blockDim.x) {
        sb1[i] = bn1[wo*FN + i];
        sb2[i] = bn2[wo*FN + i];
    }
    __syncthreads();

    const int n = blockIdx.x*blockDim.x + threadIdx.x;
    if (n >= NN) return;

    const float* xr = x      + (((size_t)p*NN + n)*CC + c)*FF;
    const float* ar = g_aggr + (((size_t)p*NN + n)*CC + c)*FF;

    float h2[FN];
    #pragma unroll
    for (int g = 0; g < FN; ++g) h2[g] = sb1[g];

    const float4* x4  = (const float4*)xr;
    const float4* a4  = (const float4*)ar;
    const float4* w14 = (const float4*)sW1;

    #pragma unroll 1
    for (int fc = 0; fc < FF/4; ++fc) {
        const float4 u = x4[fc];
        #pragma unroll
        for (int g = 0; g < FN; ++g) {
            const float4 w = w14[g*(F2/4) + fc];
            h2[g] += w.x*u.x + w.y*u.y + w.z*u.z + w.w*u.w;
        }
    }
    #pragma unroll 1
    for (int fc = 0; fc < FF/4; ++fc) {
        const float4 u = a4[fc];
        #pragma unroll
        for (int g = 0; g < FN; ++g) {
            const float4 w = w14[g*(F2/4) + (FF/4) + fc];
            h2[g] += w.x*u.x + w.y*u.y + w.z*u.z + w.w*u.w;
        }
    }
    #pragma unroll
    for (int g = 0; g < FN; ++g) h2[g] = tanhf(h2[g]);

    float* op = out + (((size_t)p*NN + n)*CC + c)*FN;
    const float4* w24 = (const float4*)sW2;

    #pragma unroll 1
    for (int gb = 0; gb < 4; ++gb) {
        float acc[16];
        #pragma unroll
        for (int g2 = 0; g2 < 16; ++g2) acc[g2] = sb2[gb*16 + g2];
        #pragma unroll
        for (int gc = 0; gc < FN/4; ++gc) {
            #pragma unroll
            for (int g2 = 0; g2 < 16; ++g2) {
                const float4 w = w24[(gb*16 + g2)*(FN/4) + gc];
                acc[g2] += w.x*h2[4*gc] + w.y*h2[4*gc+1]
                         + w.z*h2[4*gc+2] + w.w*h2[4*gc+3];
            }
        }
        #pragma unroll
        for (int g2 = 0; g2 < 16; g2 += 4) {
            float4 o;
            o.x = tanhf(acc[g2+0]);
            o.y = tanhf(acc[g2+1]);
            o.z = tanhf(acc[g2+2]);
            o.w = tanhf(acc[g2+3]);
            *(float4*)(op + gb*16 + g2) = o;
        }
    }
}

extern "C" void kernel_launch(void* const* d_in, const int* in_sizes, int n_in,
                              void* d_out, int out_size) {
    const float* x   = (const float*)d_in[0];
    const void*  ei  = d_in[1];
    const float* We1 = (const float*)d_in[2];
    const float* be1 = (const float*)d_in[3];
    const float* We2 = (const float*)d_in[4];
    const float* be2 = (const float*)d_in[5];
    const float* Wn1 = (const float*)d_in[6];
    const float* bn1 = (const float*)d_in[7];
    const float* Wn2 = (const float*)d_in[8];
    const float* bn2 = (const float*)d_in[9];
    float* out = (float*)d_out;

    const int smem_node = (FN*F2 + FN*FN + 2*FN) * (int)sizeof(float);  // 51712 B
    cudaFuncSetAttribute(node_kernel,
                         cudaFuncAttributeMaxDynamicSharedMemorySize, smem_node);

    detect_kernel<<<1, 1>>>(ei);
    zero_kernel<<<1024, 256>>>();

    dim3 ge(512, PP);
    edge_kernel<<<ge, 256>>>(x, ei, We1, be1, We2, be2);

    dim3 gn((NN + 255)/256, CC, PP);
    node_kernel<<<gn, 256, smem_node>>>(x, Wn1, bn1, Wn2, bn2, out);
}

// round 4
// speedup vs baseline: 1.2226x; 1.2226x over previous
#include <cuda_runtime.h>
#include <math.h>

#define PP 3
#define NN 50000
#define EE 256000
#define CC 5
#define FF 68
#define FE 16
#define FN 64
#define F2 (2*FF)   // 136

typedef unsigned long long ull;

#define PACK_F32X2(out, lo, hi) \
    asm("mov.b64 %0, {%1, %2};" : "=l"(out) : "f"(lo), "f"(hi))
#define UNPACK_F32X2(lo, hi, in) \
    asm("mov.b64 {%0, %1}, %2;" : "=f"(lo), "=f"(hi) : "l"(in))
#define FMA_F32X2(d, a, b, c) \
    asm("fma.rn.f32x2 %0, %1, %2, %3;" : "=l"(d) : "l"(a), "l"(b), "l"(c))

// Scratch for scatter-add aggregation: [P, N, C, F] = 51,000,000 floats (204 MB)
__device__ __align__(16) float g_aggr[(size_t)PP*NN*CC*FF];
__device__ int g_is64;   // 1 if edge_index is int64, 0 if int32

__global__ void detect_kernel(const void* __restrict__ ei) {
    const long long* q = (const long long*)ei;
    int ok = 1;
    for (int i = 0; i < 64; ++i) {
        long long v = q[i];
        if (v < 0 || v >= NN) { ok = 0; break; }
    }
    g_is64 = ok;
}

__global__ void zero_kernel() {
    const size_t total = (size_t)PP*NN*CC*FF/4;
    float4* p = (float4*)g_aggr;
    const float4 z = make_float4(0.f, 0.f, 0.f, 0.f);
    for (size_t i = (size_t)blockIdx.x*blockDim.x + threadIdx.x; i < total;
         i += (size_t)gridDim.x*blockDim.x)
        p[i] = z;
}

__device__ __forceinline__ void red4(float* addr, float a, float b, float c, float d) {
    asm volatile("red.global.add.v4.f32 [%0], {%1,%2,%3,%4};"
                 :: "l"(addr), "f"(a), "f"(b), "f"(c), "f"(d) : "memory");
}

// 16 gate outputs (8 f32x2 accumulators) += u * w[k][0..15]
__device__ __forceinline__ void fma16(ull* acc2, const float* wk, float u) {
    ull uu; PACK_F32X2(uu, u, u);
    const ulonglong2* w = (const ulonglong2*)wk;
    #pragma unroll
    for (int j = 0; j < 4; ++j) {
        ulonglong2 wv = w[j];
        FMA_F32X2(acc2[2*j+0], uu, wv.x, acc2[2*j+0]);
        FMA_F32X2(acc2[2*j+1], uu, wv.y, acc2[2*j+1]);
    }
}

// 64 gate outputs (32 f32x2 accumulators) += u * w[k][0..63]
__device__ __forceinline__ void fma64(ull* acc2, const float* wk, float u) {
    ull uu; PACK_F32X2(uu, u, u);
    const ulonglong2* w = (const ulonglong2*)wk;
    #pragma unroll
    for (int j = 0; j < 16; ++j) {
        ulonglong2 wv = w[j];
        FMA_F32X2(acc2[2*j+0], uu, wv.x, acc2[2*j+0]);
        FMA_F32X2(acc2[2*j+1], uu, wv.y, acc2[2*j+1]);
    }
}

// ---------------------------------------------------------------------------
// Edge kernel: one thread per edge. Weights staged in smem TRANSPOSED to
// [c][k][g] so the 16 gate-weights for one input scalar are contiguous ->
// ulonglong2 broadcast loads feeding packed f32x2 FMAs (2 MACs/lane/issue).
// ---------------------------------------------------------------------------
__global__ __launch_bounds__(256) void edge_kernel(
    const float* __restrict__ x, const void* __restrict__ ei,
    const float* __restrict__ We1, const float* __restrict__ be1,
    const float* __restrict__ We2, const float* __restrict__ be2)
{
    __shared__ __align__(16) float sW1t[CC*F2*FE];   // 10880 floats = 43.5 KB
    __shared__ float sb1[CC*FE];
    __shared__ float sW2[CC*FE];
    __shared__ float sb2[CC];

    const int p = blockIdx.y;
    for (int i = threadIdx.x; i < CC*F2*FE; i += blockDim.x) {
        const int c = i / (F2*FE);
        const int r = i % (F2*FE);
        const int k = r / FE;
        const int g = r % FE;
        sW1t[i] = We1[(((size_t)p*CC + c)*FE + g)*F2 + k];
    }
    for (int i = threadIdx.x; i < CC*FE; i += blockDim.x) {
        sb1[i] = be1[p*CC*FE + i];
        sW2[i] = We2[p*CC*FE + i];
    }
    if (threadIdx.x < CC) sb2[threadIdx.x] = be2[p*CC + threadIdx.x];
    __syncthreads();

    const int is64 = g_is64;
    const long long* ei64 = (const long long*)ei;
    const int*       ei32 = (const int*)ei;
    const size_t base = (size_t)p*2*EE;

    const int e = blockIdx.x*blockDim.x + threadIdx.x;   // EE % 256 == 0
    int s, d;
    if (is64) {
        s = (int)ei64[base + e];
        d = (int)ei64[base + EE + e];
    } else {
        s = ei32[base + e];
        d = ei32[base + EE + e];
    }
    const float* xi = x + ((size_t)p*NN + d)*(CC*FF);   // target feats
    const float* xj = x + ((size_t)p*NN + s)*(CC*FF);   // source feats

    float lg[CC];
    #pragma unroll 1
    for (int c = 0; c < CC; ++c) {
        ull acc2[8];
        #pragma unroll
        for (int j = 0; j < 8; ++j)
            PACK_F32X2(acc2[j], sb1[c*FE + 2*j], sb1[c*FE + 2*j + 1]);

        const float4* mi = (const float4*)(xi + c*FF);
        const float4* mj = (const float4*)(xj + c*FF);
        const float* wb = sW1t + c*F2*FE;

        #pragma unroll 1
        for (int fc = 0; fc < FF/4; ++fc) {
            const float4 u = mi[fc];
            const float* wk = wb + (4*fc)*FE;
            fma16(acc2, wk + 0*FE, u.x);
            fma16(acc2, wk + 1*FE, u.y);
            fma16(acc2, wk + 2*FE, u.z);
            fma16(acc2, wk + 3*FE, u.w);
        }
        #pragma unroll 1
        for (int fc = 0; fc < FF/4; ++fc) {
            const float4 u = mj[fc];
            const float* wk = wb + (FF + 4*fc)*FE;
            fma16(acc2, wk + 0*FE, u.x);
            fma16(acc2, wk + 1*FE, u.y);
            fma16(acc2, wk + 2*FE, u.z);
            fma16(acc2, wk + 3*FE, u.w);
        }

        float l = sb2[c];
        #pragma unroll
        for (int j = 0; j < 8; ++j) {
            float a0, a1; UNPACK_F32X2(a0, a1, acc2[j]);
            l += tanhf(a0)*sW2[c*FE + 2*j] + tanhf(a1)*sW2[c*FE + 2*j + 1];
        }
        lg[c] = l;
    }

    // softmax over classes
    float mx = lg[0];
    #pragma unroll
    for (int c = 1; c < CC; ++c) mx = fmaxf(mx, lg[c]);
    float w[CC];
    float sum = 0.f;
    #pragma unroll
    for (int c = 0; c < CC; ++c) { w[c] = expf(lg[c] - mx); sum += w[c]; }
    const float inv = 1.f / sum;

    // msg = w * x_j, scatter-add to aggr[dst]
    float* ap = g_aggr + ((size_t)p*NN + d)*(CC*FF);
    #pragma unroll
    for (int c = 0; c < CC; ++c) {
        const float wc = w[c] * inv;
        const float4* mj = (const float4*)(xj + c*FF);
        float* a = ap + c*FF;
        #pragma unroll 1
        for (int fc = 0; fc < FF/4; ++fc) {
            const float4 v = mj[fc];
            red4(a + 4*fc, wc*v.x, wc*v.y, wc*v.z, wc*v.w);
        }
    }
}

// ---------------------------------------------------------------------------
// Node kernel: one thread per (node, class). Block owns one (plane, class).
// Weights in dynamic smem transposed to [k][g]; packed f32x2 accumulators.
// ---------------------------------------------------------------------------
__global__ __launch_bounds__(256) void node_kernel(
    const float* __restrict__ x,
    const float* __restrict__ Wn1, const float* __restrict__ bn1,
    const float* __restrict__ Wn2, const float* __restrict__ bn2,
    float* __restrict__ out)
{
    extern __shared__ __align__(16) float sm[];
    float* sW1t = sm;                  // [k=136][g=64] = 8704 floats
    float* sW2t = sm + F2*FN;          // [k=64][g=64]  = 4096 floats
    float* sb1  = sW2t + FN*FN;        // 64
    float* sb2  = sb1 + FN;            // 64

    const int c = blockIdx.y;
    const int p = blockIdx.z;
    const size_t wo = (size_t)p*CC + c;
    for (int i = threadIdx.x; i < F2*FN; i += blockDim.x) {
        const int k = i / FN, g = i % FN;
        sW1t[i] = Wn1[(wo*FN + g)*F2 + k];
    }
    for (int i = threadIdx.x; i < FN*FN; i += blockDim.x) {
        const int k = i / FN, g = i % FN;
        sW2t[i] = Wn2[(wo*FN + g)*FN + k];
    }
    for (int i = threadIdx.x; i < FN; i += blockDim.x) {
        sb1[i] = bn1[wo*FN + i];
        sb2[i] = bn2[wo*FN + i];
    }
    __syncthreads();

    const int n = blockIdx.x*blockDim.x + threadIdx.x;
    if (n >= NN) return;

    const float* xr = x      + (((size_t)p*NN + n)*CC + c)*FF;
    const float* ar = g_aggr + (((size_t)p*NN + n)*CC + c)*FF;

    // ---- layer 1: h = tanh(W1 . [x, aggr] + b1), 64 outs as 32 f32x2 ----
    ull acc2[32];
    #pragma unroll
    for (int j = 0; j < 32; ++j)
        PACK_F32X2(acc2[j], sb1[2*j], sb1[2*j + 1]);

    const float4* x4 = (const float4*)xr;
    const float4* a4 = (const float4*)ar;

    #pragma unroll 1
    for (int fc = 0; fc < FF/4; ++fc) {
        const float4 u = x4[fc];
        const float* wk = sW1t + (4*fc)*FN;
        fma64(acc2, wk + 0*FN, u.x);
        fma64(acc2, wk + 1*FN, u.y);
        fma64(acc2, wk + 2*FN, u.z);
        fma64(acc2, wk + 3*FN, u.w);
    }
    #pragma unroll 1
    for (int fc = 0; fc < FF/4; ++fc) {
        const float4 u = a4[fc];
        const float* wk = sW1t + (FF + 4*fc)*FN;
        fma64(acc2, wk + 0*FN, u.x);
        fma64(acc2, wk + 1*FN, u.y);
        fma64(acc2, wk + 2*FN, u.z);
        fma64(acc2, wk + 3*FN, u.w);
    }

    float h[FN];
    #pragma unroll
    for (int j = 0; j < 32; ++j) {
        float a0, a1; UNPACK_F32X2(a0, a1, acc2[j]);
        h[2*j]   = tanhf(a0);
        h[2*j+1] = tanhf(a1);
    }

    // ---- layer 2: out = tanh(W2 . h + b2), in 16-wide output chunks ----
    float* op = out + (((size_t)p*NN + n)*CC + c)*FN;
    #pragma unroll 1
    for (int gb = 0; gb < 4; ++gb) {
        ull a2[8];
        #pragma unroll
        for (int j = 0; j < 8; ++j)
            PACK_F32X2(a2[j], sb2[gb*16 + 2*j], sb2[gb*16 + 2*j + 1]);

        #pragma unroll 4
        for (int k = 0; k < FN; ++k)
            fma16(a2, sW2t + k*FN + gb*16, h[k]);

        #pragma unroll
        for (int j = 0; j < 8; j += 2) {
            float a0, a1, b0, b1;
            UNPACK_F32X2(a0, a1, a2[j]);
            UNPACK_F32X2(b0, b1, a2[j+1]);
            float4 o;
            o.x = tanhf(a0); o.y = tanhf(a1);
            o.z = tanhf(b0); o.w = tanhf(b1);
            *(float4*)(op + gb*16 + 2*j) = o;
        }
    }
}

extern "C" void kernel_launch(void* const* d_in, const int* in_sizes, int n_in,
                              void* d_out, int out_size) {
    const float* x   = (const float*)d_in[0];
    const void*  ei  = d_in[1];
    const float* We1 = (const float*)d_in[2];
    const float* be1 = (const float*)d_in[3];
    const float* We2 = (const float*)d_in[4];
    const float* be2 = (const float*)d_in[5];
    const float* Wn1 = (const float*)d_in[6];
    const float* bn1 = (const float*)d_in[7];
    const float* Wn2 = (const float*)d_in[8];
    const float* bn2 = (const float*)d_in[9];
    float* out = (float*)d_out;

    const int smem_node = (F2*FN + FN*FN + 2*FN) * (int)sizeof(float);  // 51712 B
    cudaFuncSetAttribute(node_kernel,
                         cudaFuncAttributeMaxDynamicSharedMemorySize, smem_node);

    detect_kernel<<<1, 1>>>(ei);
    zero_kernel<<<1024, 256>>>();

    dim3 ge(EE/256, PP);
    edge_kernel<<<ge, 256>>>(x, ei, We1, be1, We2, be2);

    dim3 gn((NN + 255)/256, CC, PP);
    node_kernel<<<gn, 256, smem_node>>>(x, Wn1, bn1, Wn2, bn2, out);
}